// round 5
// baseline (speedup 1.0000x reference)
#include <cuda_runtime.h>
#include <cuda_bf16.h>
#include <cstddef>

// GCN_48129403519136: 2-layer GCN + mean-pool + FC + log_softmax
// Buffers (fixed roles, no aliasing):
//   g_bufA: gemm1 raw h1 -> (overwritten) gemm2 raw h2 -> pool summ
//   g_bufB: layer1 agg  -> layer2 input -> layer2 agg (pre-activation)
// Flow:
//   gemm1: A=x            -> C=g_bufA (h1 raw),  Cs=g_bufB (h1*dinv^2)
//   scat1: g_bufB[dst] += g_bufA[src]*norm
//   gemm2: A=g_bufB (fused relu+b1) -> C=g_bufA (h2 raw), Cs=g_bufB (h2*dinv^2)
//          (each block reads its own rows of g_bufB fully before writing them)
//   scat2: g_bufB[dst] += g_bufA[src]*norm      -> g_bufB = layer2 pre-act agg
//   zero : g_bufA = 0, g_cnt = 0                (g_bufA free after scat2)
//   pool : g_bufA[dict[i]] += relu(g_bufB[i]+b2); g_cnt[dict[i]] += 1
//   final: out = log_softmax( (g_bufA[i]/max(cnt,1)) @ Wfc + bfc )

#define N_MAX 100000
#define E_MAX 1600000
#define F_HID 64

static __device__ float g_bufA[N_MAX * F_HID];
static __device__ float g_bufB[N_MAX * F_HID];
static __device__ float g_dinv[N_MAX];
static __device__ float g_norm[E_MAX];
static __device__ float g_cnt[N_MAX];
static __device__ int   g_deg[N_MAX];

__global__ void zero_deg_kernel(int n) {
    int i = blockIdx.x * blockDim.x + threadIdx.x;
    if (i < n) g_deg[i] = 0;
}

__global__ void count_kernel(const int* __restrict__ dst, int E) {
    int e = blockIdx.x * blockDim.x + threadIdx.x;
    if (e < E) atomicAdd(&g_deg[dst[e]], 1);
}

__global__ void dinv_kernel(int n) {
    int i = blockIdx.x * blockDim.x + threadIdx.x;
    if (i < n) g_dinv[i] = rsqrtf((float)g_deg[i] + 1.0f);
}

__global__ void norm_kernel(const int* __restrict__ src, const int* __restrict__ dst, int E) {
    int e = blockIdx.x * blockDim.x + threadIdx.x;
    if (e < E) g_norm[e] = g_dinv[src[e]] * g_dinv[dst[e]];
}

// zero pool accumulators: summ = g_bufA, cnt = g_cnt
__global__ void zero_pool_kernel(int n) {
    int i = blockIdx.x * blockDim.x + threadIdx.x;
    if (i < n * F_HID) g_bufA[i] = 0.0f;
    if (i < n) g_cnt[i] = 0.0f;
}

// C[n x 64] = A[n x K] @ W[K x 64]; optional relu(a + bias_in[k]) on A-load;
// dual epilogue: C (raw) and Cs = C * dinv[row]^2 (GCN self-loop term).
// 256 threads, 128x64 tile, BK=32, per-thread 8x4 microtile, LDS.128 feeds.
template <int K, bool RELU_IN>
__global__ __launch_bounds__(256) void gemm_dual_kernel(
    const float* __restrict__ A, const float* __restrict__ W,
    const float* __restrict__ bias_in,
    float* __restrict__ C, float* __restrict__ Cs, int n)
{
    constexpr int F = 64, BK = 32, BM = 128;
    __shared__ float As[BK][BM + 4];   // transposed A tile; +4 keeps float4 alignment
    __shared__ float Ws[BK][F];

    const int tid = threadIdx.x;
    const int tx = tid & 15;           // 16 col-groups x 4 cols
    const int ty = tid >> 4;           // 16 row-groups x 8 rows
    const int row0 = blockIdx.x * BM;

    float acc[8][4];
#pragma unroll
    for (int i = 0; i < 8; i++)
#pragma unroll
        for (int j = 0; j < 4; j++) acc[i][j] = 0.0f;

    for (int kc = 0; kc < K; kc += BK) {
#pragma unroll
        for (int i = 0; i < (BM * BK) / 256; i++) {
            int idx = tid + i * 256;
            int k = idx & (BK - 1);
            int r = idx >> 5;
            int grow = row0 + r;
            float v = 0.0f;
            if (grow < n) v = A[(size_t)grow * K + kc + k];
            if (RELU_IN) v = fmaxf(v + bias_in[kc + k], 0.0f);
            As[k][r] = v;
        }
#pragma unroll
        for (int i = 0; i < (BK * F) / 256; i++) {
            int idx = tid + i * 256;
            int k = idx >> 6;
            int f = idx & 63;
            Ws[k][f] = W[(size_t)(kc + k) * F + f];
        }
        __syncthreads();

#pragma unroll
        for (int k = 0; k < BK; k++) {
            float4 a0 = *(const float4*)&As[k][ty * 8];
            float4 a1 = *(const float4*)&As[k][ty * 8 + 4];
            float4 b  = *(const float4*)&Ws[k][tx * 4];
            float av[8] = {a0.x, a0.y, a0.z, a0.w, a1.x, a1.y, a1.z, a1.w};
            float bv[4] = {b.x, b.y, b.z, b.w};
#pragma unroll
            for (int i = 0; i < 8; i++)
#pragma unroll
                for (int j = 0; j < 4; j++)
                    acc[i][j] = fmaf(av[i], bv[j], acc[i][j]);
        }
        __syncthreads();
    }

#pragma unroll
    for (int i = 0; i < 8; i++) {
        int row = row0 + ty * 8 + i;
        if (row < n) {
            float dv = g_dinv[row];
            float s = dv * dv;
            float4 c = make_float4(acc[i][0], acc[i][1], acc[i][2], acc[i][3]);
            *(float4*)&C[(size_t)row * F + tx * 4] = c;
            float4 cs = make_float4(c.x * s, c.y * s, c.z * s, c.w * s);
            *(float4*)&Cs[(size_t)row * F + tx * 4] = cs;
        }
    }
}

__device__ __forceinline__ void red_add_v4(float* p, float4 w) {
    asm volatile("red.global.add.v4.f32 [%0], {%1, %2, %3, %4};"
                 :: "l"(p), "f"(w.x), "f"(w.y), "f"(w.z), "f"(w.w)
                 : "memory");
}

// agg[dst] += h[src] * norm   (16 lanes per edge, one float4 per lane)
__global__ void scatter_kernel(const float* __restrict__ h, float* __restrict__ agg,
                               const int* __restrict__ src, const int* __restrict__ dst,
                               int E)
{
    int t = blockIdx.x * blockDim.x + threadIdx.x;
    int e = t >> 4;
    if (e >= E) return;
    int lane = t & 15;
    int s = __ldg(&src[e]);
    int d = __ldg(&dst[e]);
    float nm = __ldg(&g_norm[e]);
    float4 v = *(const float4*)(h + (size_t)s * F_HID + lane * 4);
    float4 w = make_float4(v.x * nm, v.y * nm, v.z * nm, v.w * nm);
    red_add_v4(agg + (size_t)d * F_HID + lane * 4, w);
}

// g_bufA[dict[i]] += relu(g_bufB[i] + b2); g_cnt[dict[i]] += 1
__global__ void pool_kernel(const float* __restrict__ b2,
                            const int* __restrict__ dict, int n)
{
    int t = blockIdx.x * blockDim.x + threadIdx.x;
    int i = t >> 4;
    if (i >= n) return;
    int lane = t & 15;
    int d = __ldg(&dict[i]);
    float4 v = *(const float4*)(&g_bufB[(size_t)i * F_HID + lane * 4]);
    float4 bb = *(const float4*)(b2 + lane * 4);
    float4 w = make_float4(fmaxf(v.x + bb.x, 0.0f), fmaxf(v.y + bb.y, 0.0f),
                           fmaxf(v.z + bb.z, 0.0f), fmaxf(v.w + bb.w, 0.0f));
    red_add_v4(&g_bufA[(size_t)d * F_HID + lane * 4], w);
    if (lane == 0) atomicAdd(&g_cnt[d], 1.0f);
}

// out = log_softmax( (g_bufA[i] / max(cnt,1)) @ Wfc + bfc )
__global__ __launch_bounds__(256) void final_kernel(
    const float* __restrict__ Wfc, const float* __restrict__ bfc,
    float* __restrict__ out, int n)
{
    __shared__ float Wsh[64 * 16];
    __shared__ float bsh[16];
    for (int i = threadIdx.x; i < 64 * 16; i += blockDim.x) Wsh[i] = Wfc[i];
    if (threadIdx.x < 16) bsh[threadIdx.x] = bfc[threadIdx.x];
    __syncthreads();

    int i = blockIdx.x * blockDim.x + threadIdx.x;
    if (i >= n) return;
    float inv = 1.0f / fmaxf(g_cnt[i], 1.0f);

    float lg[16];
#pragma unroll
    for (int j = 0; j < 16; j++) lg[j] = bsh[j];
#pragma unroll
    for (int f = 0; f < 64; f++) {
        float p = g_bufA[(size_t)i * F_HID + f] * inv;
#pragma unroll
        for (int j = 0; j < 16; j++) lg[j] = fmaf(p, Wsh[f * 16 + j], lg[j]);
    }
    float m = lg[0];
#pragma unroll
    for (int j = 1; j < 16; j++) m = fmaxf(m, lg[j]);
    float ssum = 0.0f;
#pragma unroll
    for (int j = 0; j < 16; j++) ssum += expf(lg[j] - m);
    float lse = m + logf(ssum);
#pragma unroll
    for (int j = 0; j < 16; j++) out[(size_t)i * 16 + j] = lg[j] - lse;
}

extern "C" void kernel_launch(void* const* d_in, const int* in_sizes, int n_in,
                              void* d_out, int out_size)
{
    const float* x    = (const float*)d_in[0];
    const int*   edge = (const int*)d_in[1];
    const int*   dict = (const int*)d_in[2];
    const float* W1   = (const float*)d_in[3];
    const float* b1   = (const float*)d_in[4];
    const float* W2   = (const float*)d_in[5];
    const float* b2   = (const float*)d_in[6];
    const float* Wfc  = (const float*)d_in[7];
    const float* bfc  = (const float*)d_in[8];
    float* out = (float*)d_out;

    int n = in_sizes[0] / 128;
    int E = in_sizes[1] / 2;
    if (n > N_MAX) n = N_MAX;
    if (E > E_MAX) E = E_MAX;
    const int* src = edge;
    const int* dst = edge + E;

    void *pA = nullptr, *pB = nullptr;
    cudaGetSymbolAddress(&pA, g_bufA);
    cudaGetSymbolAddress(&pB, g_bufB);
    float* bufA = (float*)pA;
    float* bufB = (float*)pB;

    const int T = 256;
    int gb_n   = (n + T - 1) / T;
    int gb_e   = (E + T - 1) / T;
    int gb_row = (n + 127) / 128;
    int gb_sc  = (E * 16 + T - 1) / T;
    int gb_pl  = (n * 16 + T - 1) / T;
    int gb_zp  = (n * F_HID + T - 1) / T;

    // normalization
    zero_deg_kernel<<<gb_n, T>>>(n);
    count_kernel<<<gb_e, T>>>(dst, E);
    dinv_kernel<<<gb_n, T>>>(n);
    norm_kernel<<<gb_e, T>>>(src, dst, E);

    // layer 1
    gemm_dual_kernel<128, false><<<gb_row, T>>>(x, W1, b1, bufA, bufB, n);
    scatter_kernel<<<gb_sc, T>>>(bufA, bufB, src, dst, E);

    // layer 2 (relu(+b1) fused into A-load; in-place-safe Cs write)
    gemm_dual_kernel<64, true><<<gb_row, T>>>(bufB, W2, b1, bufA, bufB, n);
    scatter_kernel<<<gb_sc, T>>>(bufA, bufB, src, dst, E);

    // pooling + head
    zero_pool_kernel<<<gb_zp, T>>>(n);
    pool_kernel<<<gb_pl, T>>>(b2, dict, n);
    final_kernel<<<gb_n, T>>>(Wfc, bfc, out, n);
}

// round 9
// speedup vs baseline: 1.3736x; 1.3736x over previous
#include <cuda_runtime.h>
#include <cuda_bf16.h>
#include <cstddef>

// GCN_48129403519136: 2-layer GCN + mean-pool + FC + log_softmax
// CSR-gather formulation (no float atomics in aggregation):
//   deg = indegree(dst); dinv = rsqrt(deg+1)
//   CSR: off = exclusive_scan(deg); adj[off[d]..] = src of edges into d
//   gemm1: bufA = x@W1
//   gather1: bufB[d] = sum_{s in adj(d)} bufA[s]*dinv[s]*dinv[d] + bufA[d]*dinv[d]^2
//   gemm2: bufA = relu(bufB + b1)@W2        (relu+bias fused into A-load)
//   gather2: bufB[d] = ... same with bufA
//   pool: bufA[dict[i]] += relu(bufB[i]+b2); cnt[dict[i]]++   (red.v4, 100K rows)
//   final: out = log_softmax((bufA/max(cnt,1))@Wfc + bfc)

#define N_MAX 100000
#define E_MAX 1600000
#define F_HID 64
#define SCAN_B 1024

static __device__ float g_bufA[N_MAX * F_HID];
static __device__ float g_bufB[N_MAX * F_HID];
static __device__ float g_dinv[N_MAX];
static __device__ float g_cnt[N_MAX];
static __device__ int   g_deg[N_MAX];
static __device__ int   g_off[N_MAX + 1];
static __device__ int   g_cur[N_MAX];
static __device__ int   g_adj[E_MAX];
static __device__ int   g_part[512];

// ---------------------------------------------------------------------------
// degree count (int4-vectorized, 4 edges/thread)
// ---------------------------------------------------------------------------
__global__ void count_kernel(const int* __restrict__ dst, int E) {
    int t = blockIdx.x * blockDim.x + threadIdx.x;
    int e0 = t * 4;
    if (e0 + 3 < E) {
        int4 d = *(const int4*)(dst + e0);
        atomicAdd(&g_deg[d.x], 1);
        atomicAdd(&g_deg[d.y], 1);
        atomicAdd(&g_deg[d.z], 1);
        atomicAdd(&g_deg[d.w], 1);
    } else {
        for (int e = e0; e < E; e++) atomicAdd(&g_deg[dst[e]], 1);
    }
}

// ---------------------------------------------------------------------------
// scan stage 1: per-block exclusive scan of deg -> off, block sums -> g_part.
// Also computes dinv (fused).
// ---------------------------------------------------------------------------
__global__ __launch_bounds__(SCAN_B) void scan1_kernel(int n) {
    __shared__ int sh[SCAN_B];
    int i = blockIdx.x * SCAN_B + threadIdx.x;
    int v = (i < n) ? g_deg[i] : 0;
    if (i < n) g_dinv[i] = rsqrtf((float)v + 1.0f);
    sh[threadIdx.x] = v;
    __syncthreads();
#pragma unroll
    for (int ofs = 1; ofs < SCAN_B; ofs <<= 1) {
        int t = (threadIdx.x >= ofs) ? sh[threadIdx.x - ofs] : 0;
        __syncthreads();
        sh[threadIdx.x] += t;
        __syncthreads();
    }
    if (i < n) g_off[i] = sh[threadIdx.x] - v;   // exclusive
    if (threadIdx.x == SCAN_B - 1) g_part[blockIdx.x] = sh[SCAN_B - 1];
}

// scan stage 2: exclusive scan of block partials (single block, nb <= 512)
__global__ __launch_bounds__(512) void scan2_kernel(int nb) {
    __shared__ int sh[512];
    int tid = threadIdx.x;
    int v = (tid < nb) ? g_part[tid] : 0;
    sh[tid] = v;
    __syncthreads();
#pragma unroll
    for (int ofs = 1; ofs < 512; ofs <<= 1) {
        int t = (tid >= ofs) ? sh[tid - ofs] : 0;
        __syncthreads();
        sh[tid] += t;
        __syncthreads();
    }
    if (tid < nb) g_part[tid] = sh[tid] - v;     // exclusive
}

// scan stage 3: add block offsets; init cursors; off[n] = E
__global__ void scan3_kernel(int n, int E) {
    int i = blockIdx.x * blockDim.x + threadIdx.x;
    if (i < n) {
        int o = g_off[i] + g_part[i >> 10];
        g_off[i] = o;
        g_cur[i] = o;
    }
    if (i == 0) g_off[n] = E;
}

// CSR fill: adj[pos(dst)] = src   (int4-vectorized)
__global__ void fill_kernel(const int* __restrict__ src, const int* __restrict__ dst, int E) {
    int t = blockIdx.x * blockDim.x + threadIdx.x;
    int e0 = t * 4;
    if (e0 + 3 < E) {
        int4 d = *(const int4*)(dst + e0);
        int4 s = *(const int4*)(src + e0);
        g_adj[atomicAdd(&g_cur[d.x], 1)] = s.x;
        g_adj[atomicAdd(&g_cur[d.y], 1)] = s.y;
        g_adj[atomicAdd(&g_cur[d.z], 1)] = s.z;
        g_adj[atomicAdd(&g_cur[d.w], 1)] = s.w;
    } else {
        for (int e = e0; e < E; e++)
            g_adj[atomicAdd(&g_cur[dst[e]], 1)] = src[e];
    }
}

// ---------------------------------------------------------------------------
// GEMM: C[n x 64] = A[n x K] @ W[K x 64]; optional relu(a + bias_in[k]) fused.
// 256 threads, 128x64 tile, BK=32, per-thread 8x4 microtile.
// ---------------------------------------------------------------------------
template <int K, bool RELU_IN>
__global__ __launch_bounds__(256) void gemm_kernel(
    const float* __restrict__ A, const float* __restrict__ W,
    const float* __restrict__ bias_in, float* __restrict__ C, int n)
{
    constexpr int F = 64, BK = 32, BM = 128;
    __shared__ float As[BK][BM + 4];
    __shared__ float Ws[BK][F];

    const int tid = threadIdx.x;
    const int tx = tid & 15;
    const int ty = tid >> 4;
    const int row0 = blockIdx.x * BM;

    float acc[8][4];
#pragma unroll
    for (int i = 0; i < 8; i++)
#pragma unroll
        for (int j = 0; j < 4; j++) acc[i][j] = 0.0f;

    for (int kc = 0; kc < K; kc += BK) {
#pragma unroll
        for (int i = 0; i < (BM * BK) / 256; i++) {
            int idx = tid + i * 256;
            int k = idx & (BK - 1);
            int r = idx >> 5;
            int grow = row0 + r;
            float v = 0.0f;
            if (grow < n) v = A[(size_t)grow * K + kc + k];
            if (RELU_IN) v = fmaxf(v + bias_in[kc + k], 0.0f);
            As[k][r] = v;
        }
#pragma unroll
        for (int i = 0; i < (BK * F) / 256; i++) {
            int idx = tid + i * 256;
            int k = idx >> 6;
            int f = idx & 63;
            Ws[k][f] = W[(size_t)(kc + k) * F + f];
        }
        __syncthreads();

#pragma unroll
        for (int k = 0; k < BK; k++) {
            float4 a0 = *(const float4*)&As[k][ty * 8];
            float4 a1 = *(const float4*)&As[k][ty * 8 + 4];
            float4 b  = *(const float4*)&Ws[k][tx * 4];
            float av[8] = {a0.x, a0.y, a0.z, a0.w, a1.x, a1.y, a1.z, a1.w};
            float bv[4] = {b.x, b.y, b.z, b.w};
#pragma unroll
            for (int i = 0; i < 8; i++)
#pragma unroll
                for (int j = 0; j < 4; j++)
                    acc[i][j] = fmaf(av[i], bv[j], acc[i][j]);
        }
        __syncthreads();
    }

#pragma unroll
    for (int i = 0; i < 8; i++) {
        int row = row0 + ty * 8 + i;
        if (row < n) {
            float4 c = make_float4(acc[i][0], acc[i][1], acc[i][2], acc[i][3]);
            *(float4*)&C[(size_t)row * F + tx * 4] = c;
        }
    }
}

// ---------------------------------------------------------------------------
// CSR gather aggregation: one warp per node.
//   agg[d] = sum_{s in adj(d)} h[s]*dinv[s]*dinv[d]  +  h[d]*dinv[d]^2
// Lanes: f = lane&15 (float4 slot), p = lane>>4 (edge parity).
// Unrolled x2 per lane: 4 edges in flight per warp (2 LDG.128 per lane per
// iteration) to double MLP on the random h[src] gathers. Tail edges are
// masked with a zero weight (row-0 load contributes v*0 = 0).
// ---------------------------------------------------------------------------
__global__ __launch_bounds__(256) void gather_kernel(
    const float* __restrict__ h, float* __restrict__ agg, int n)
{
    int w = (blockIdx.x * blockDim.x + threadIdx.x) >> 5;
    if (w >= n) return;
    int lane = threadIdx.x & 31;
    int f = lane & 15;
    int p = lane >> 4;

    int beg = g_off[w];
    int end = g_off[w + 1];
    float dv = g_dinv[w];

    float4 acc = make_float4(0.f, 0.f, 0.f, 0.f);

    for (int j = beg + p; j < end; j += 4) {
        int j1 = j + 2;
        int s0 = __ldg(&g_adj[j]);
        int s1 = (j1 < end) ? __ldg(&g_adj[j1]) : 0;
        float w0 = __ldg(&g_dinv[s0]) * dv;
        float w1 = (j1 < end) ? (__ldg(&g_dinv[s1]) * dv) : 0.0f;
        float4 v0 = *(const float4*)(h + (size_t)s0 * F_HID + f * 4);
        float4 v1 = *(const float4*)(h + (size_t)s1 * F_HID + f * 4);
        acc.x = fmaf(v0.x, w0, acc.x);
        acc.y = fmaf(v0.y, w0, acc.y);
        acc.z = fmaf(v0.z, w0, acc.z);
        acc.w = fmaf(v0.w, w0, acc.w);
        acc.x = fmaf(v1.x, w1, acc.x);
        acc.y = fmaf(v1.y, w1, acc.y);
        acc.z = fmaf(v1.z, w1, acc.z);
        acc.w = fmaf(v1.w, w1, acc.w);
    }
    // combine the two edge-parity halves (lane f <-> lane f+16)
    acc.x += __shfl_xor_sync(0xffffffffu, acc.x, 16);
    acc.y += __shfl_xor_sync(0xffffffffu, acc.y, 16);
    acc.z += __shfl_xor_sync(0xffffffffu, acc.z, 16);
    acc.w += __shfl_xor_sync(0xffffffffu, acc.w, 16);

    if (p == 0) {
        float s2 = dv * dv;
        float4 self = *(const float4*)(h + (size_t)w * F_HID + f * 4);
        float4 o = make_float4(fmaf(self.x, s2, acc.x), fmaf(self.y, s2, acc.y),
                               fmaf(self.z, s2, acc.z), fmaf(self.w, s2, acc.w));
        *(float4*)(agg + (size_t)w * F_HID + f * 4) = o;
    }
}

// ---------------------------------------------------------------------------
// pool: bufA[dict[i]] += relu(bufB[i] + b2); cnt[dict[i]] += 1
// ---------------------------------------------------------------------------
__device__ __forceinline__ void red_add_v4(float* p, float4 w) {
    asm volatile("red.global.add.v4.f32 [%0], {%1, %2, %3, %4};"
                 :: "l"(p), "f"(w.x), "f"(w.y), "f"(w.z), "f"(w.w)
                 : "memory");
}

__global__ void pool_kernel(const float* __restrict__ b2,
                            const int* __restrict__ dict, int n)
{
    int t = blockIdx.x * blockDim.x + threadIdx.x;
    int i = t >> 4;
    if (i >= n) return;
    int lane = t & 15;
    int d = __ldg(&dict[i]);
    float4 v = *(const float4*)(&g_bufB[(size_t)i * F_HID + lane * 4]);
    float4 bb = *(const float4*)(b2 + lane * 4);
    float4 w = make_float4(fmaxf(v.x + bb.x, 0.0f), fmaxf(v.y + bb.y, 0.0f),
                           fmaxf(v.z + bb.z, 0.0f), fmaxf(v.w + bb.w, 0.0f));
    red_add_v4(&g_bufA[(size_t)d * F_HID + lane * 4], w);
    if (lane == 0) atomicAdd(&g_cnt[d], 1.0f);
}

// out = log_softmax( (bufA[i] / max(cnt,1)) @ Wfc + bfc )
__global__ __launch_bounds__(256) void final_kernel(
    const float* __restrict__ Wfc, const float* __restrict__ bfc,
    float* __restrict__ out, int n)
{
    __shared__ float Wsh[64 * 16];
    __shared__ float bsh[16];
    for (int i = threadIdx.x; i < 64 * 16; i += blockDim.x) Wsh[i] = Wfc[i];
    if (threadIdx.x < 16) bsh[threadIdx.x] = bfc[threadIdx.x];
    __syncthreads();

    int i = blockIdx.x * blockDim.x + threadIdx.x;
    if (i >= n) return;
    float inv = 1.0f / fmaxf(g_cnt[i], 1.0f);

    float lg[16];
#pragma unroll
    for (int j = 0; j < 16; j++) lg[j] = bsh[j];
#pragma unroll
    for (int f = 0; f < 64; f++) {
        float p = g_bufA[(size_t)i * F_HID + f] * inv;
#pragma unroll
        for (int j = 0; j < 16; j++) lg[j] = fmaf(p, Wsh[f * 16 + j], lg[j]);
    }
    float m = lg[0];
#pragma unroll
    for (int j = 1; j < 16; j++) m = fmaxf(m, lg[j]);
    float ssum = 0.0f;
#pragma unroll
    for (int j = 0; j < 16; j++) ssum += expf(lg[j] - m);
    float lse = m + logf(ssum);
#pragma unroll
    for (int j = 0; j < 16; j++) out[(size_t)i * 16 + j] = lg[j] - lse;
}

extern "C" void kernel_launch(void* const* d_in, const int* in_sizes, int n_in,
                              void* d_out, int out_size)
{
    const float* x    = (const float*)d_in[0];
    const int*   edge = (const int*)d_in[1];
    const int*   dict = (const int*)d_in[2];
    const float* W1   = (const float*)d_in[3];
    const float* b1   = (const float*)d_in[4];
    const float* W2   = (const float*)d_in[5];
    const float* b2   = (const float*)d_in[6];
    const float* Wfc  = (const float*)d_in[7];
    const float* bfc  = (const float*)d_in[8];
    float* out = (float*)d_out;

    int n = in_sizes[0] / 128;
    int E = in_sizes[1] / 2;
    if (n > N_MAX) n = N_MAX;
    if (E > E_MAX) E = E_MAX;
    const int* src = edge;
    const int* dst = edge + E;

    void *pA = nullptr, *pB = nullptr, *pDeg = nullptr, *pCnt = nullptr;
    cudaGetSymbolAddress(&pA, g_bufA);
    cudaGetSymbolAddress(&pB, g_bufB);
    cudaGetSymbolAddress(&pDeg, g_deg);
    cudaGetSymbolAddress(&pCnt, g_cnt);
    float* bufA = (float*)pA;
    float* bufB = (float*)pB;

    const int T = 256;
    int gb_n    = (n + T - 1) / T;
    int gb_e4   = ((E + 3) / 4 + T - 1) / T;
    int gb_row  = (n + 127) / 128;
    int gb_gath = (n * 32 + T - 1) / T;
    int gb_pl   = (n * 16 + T - 1) / T;
    int nb      = (n + SCAN_B - 1) / SCAN_B;

    // CSR build + normalization terms
    cudaMemsetAsync(pDeg, 0, (size_t)n * sizeof(int));
    count_kernel<<<gb_e4, T>>>(dst, E);
    scan1_kernel<<<nb, SCAN_B>>>(n);          // also computes dinv
    scan2_kernel<<<1, 512>>>(nb);
    scan3_kernel<<<gb_n, T>>>(n, E);
    fill_kernel<<<gb_e4, T>>>(src, dst, E);

    // layer 1
    gemm_kernel<128, false><<<gb_row, T>>>(x, W1, b1, bufA, n);
    gather_kernel<<<gb_gath, T>>>(bufA, bufB, n);

    // layer 2 (relu(+b1) fused into A-load)
    gemm_kernel<64, true><<<gb_row, T>>>(bufB, W2, b1, bufA, n);
    gather_kernel<<<gb_gath, T>>>(bufA, bufB, n);

    // pooling + head
    cudaMemsetAsync(pA, 0, (size_t)n * F_HID * sizeof(float));
    cudaMemsetAsync(pCnt, 0, (size_t)n * sizeof(float));
    pool_kernel<<<gb_pl, T>>>(b2, dict, n);
    final_kernel<<<gb_n, T>>>(Wfc, bfc, out, n);
}

// round 10
// speedup vs baseline: 1.4519x; 1.0570x over previous
#include <cuda_runtime.h>
#include <cuda_bf16.h>
#include <cstddef>

// GCN_48129403519136: 2-layer GCN + mean-pool + FC + log_softmax
// CSR-gather with pre-scaled features:
//   hs = (A@W)*dinv[row]  (scaling fused into GEMM epilogue)
//   agg[d] = dinv[d] * ( sum_{s in adj(d)} hs[s] + hs[d] )     [exact algebra]
//   gather2 fuses the mean-pool accumulation (agg2 never materialized).
// Flow:
//   deg/scan -> CSR (fill destructively bumps g_off; beg = off-deg)
//   gemm1: bufA = (x@W1)*dinv
//   gather1: bufB[d] = dinv[d]*(sum hs1 + self)     (raw pre-activation agg)
//   gemm2: bufA = (relu(bufB+b1)@W2)*dinv
//   gather2+pool: summ(bufB)[dict[d]] += relu(dinv[d]*(sum hs2 + self) + b2)
//   final: out = log_softmax((bufB/max(cnt,1))@Wfc + bfc)

#define N_MAX 100000
#define E_MAX 1600000
#define F_HID 64
#define SCAN_B 1024

static __device__ float g_bufA[N_MAX * F_HID];
static __device__ float g_bufB[N_MAX * F_HID];
static __device__ float g_dinv[N_MAX];
static __device__ float g_cnt[N_MAX];
static __device__ int   g_deg[N_MAX];
static __device__ int   g_off[N_MAX];      // post-fill: END of each node's range
static __device__ int   g_adj[E_MAX];
static __device__ int   g_part[512];

// ---------------------------------------------------------------------------
// degree count (int4-vectorized, 4 edges/thread)
// ---------------------------------------------------------------------------
__global__ void count_kernel(const int* __restrict__ dst, int E) {
    int t = blockIdx.x * blockDim.x + threadIdx.x;
    int e0 = t * 4;
    if (e0 + 3 < E) {
        int4 d = *(const int4*)(dst + e0);
        atomicAdd(&g_deg[d.x], 1);
        atomicAdd(&g_deg[d.y], 1);
        atomicAdd(&g_deg[d.z], 1);
        atomicAdd(&g_deg[d.w], 1);
    } else {
        for (int e = e0; e < E; e++) atomicAdd(&g_deg[dst[e]], 1);
    }
}

// ---------------------------------------------------------------------------
// scan stage 1: per-block exclusive scan of deg -> off; block sums -> g_part;
// dinv computed fused.
// ---------------------------------------------------------------------------
__global__ __launch_bounds__(SCAN_B) void scan1_kernel(int n) {
    __shared__ int sh[SCAN_B];
    int i = blockIdx.x * SCAN_B + threadIdx.x;
    int v = (i < n) ? g_deg[i] : 0;
    if (i < n) g_dinv[i] = rsqrtf((float)v + 1.0f);
    sh[threadIdx.x] = v;
    __syncthreads();
#pragma unroll
    for (int ofs = 1; ofs < SCAN_B; ofs <<= 1) {
        int t = (threadIdx.x >= ofs) ? sh[threadIdx.x - ofs] : 0;
        __syncthreads();
        sh[threadIdx.x] += t;
        __syncthreads();
    }
    if (i < n) g_off[i] = sh[threadIdx.x] - v;   // exclusive
    if (threadIdx.x == SCAN_B - 1) g_part[blockIdx.x] = sh[SCAN_B - 1];
}

// scan stage 2: exclusive scan of block partials (single block, nb <= 512)
__global__ __launch_bounds__(512) void scan2_kernel(int nb) {
    __shared__ int sh[512];
    int tid = threadIdx.x;
    int v = (tid < nb) ? g_part[tid] : 0;
    sh[tid] = v;
    __syncthreads();
#pragma unroll
    for (int ofs = 1; ofs < 512; ofs <<= 1) {
        int t = (tid >= ofs) ? sh[tid - ofs] : 0;
        __syncthreads();
        sh[tid] += t;
        __syncthreads();
    }
    if (tid < nb) g_part[tid] = sh[tid] - v;     // exclusive
}

// scan stage 3: add block offsets (g_off = global exclusive start)
__global__ void scan3_kernel(int n) {
    int i = blockIdx.x * blockDim.x + threadIdx.x;
    if (i < n) g_off[i] += g_part[i >> 10];
}

// CSR fill: destructively bumps g_off; afterwards g_off[d] = end of range.
__global__ void fill_kernel(const int* __restrict__ src, const int* __restrict__ dst, int E) {
    int t = blockIdx.x * blockDim.x + threadIdx.x;
    int e0 = t * 4;
    if (e0 + 3 < E) {
        int4 d = *(const int4*)(dst + e0);
        int4 s = *(const int4*)(src + e0);
        g_adj[atomicAdd(&g_off[d.x], 1)] = s.x;
        g_adj[atomicAdd(&g_off[d.y], 1)] = s.y;
        g_adj[atomicAdd(&g_off[d.z], 1)] = s.z;
        g_adj[atomicAdd(&g_off[d.w], 1)] = s.w;
    } else {
        for (int e = e0; e < E; e++)
            g_adj[atomicAdd(&g_off[dst[e]], 1)] = src[e];
    }
}

// ---------------------------------------------------------------------------
// GEMM: C[n x 64] = (A[n x K] @ W[K x 64]) * dinv[row]; optional fused
// relu(a + bias_in[k]) on A-load. 256 threads, 128x64 tile, BK=32, 8x4 micro.
// ---------------------------------------------------------------------------
template <int K, bool RELU_IN>
__global__ __launch_bounds__(256) void gemm_kernel(
    const float* __restrict__ A, const float* __restrict__ W,
    const float* __restrict__ bias_in, float* __restrict__ C, int n)
{
    constexpr int F = 64, BK = 32, BM = 128;
    __shared__ float As[BK][BM + 4];
    __shared__ float Ws[BK][F];

    const int tid = threadIdx.x;
    const int tx = tid & 15;
    const int ty = tid >> 4;
    const int row0 = blockIdx.x * BM;

    float acc[8][4];
#pragma unroll
    for (int i = 0; i < 8; i++)
#pragma unroll
        for (int j = 0; j < 4; j++) acc[i][j] = 0.0f;

    for (int kc = 0; kc < K; kc += BK) {
#pragma unroll
        for (int i = 0; i < (BM * BK) / 256; i++) {
            int idx = tid + i * 256;
            int k = idx & (BK - 1);
            int r = idx >> 5;
            int grow = row0 + r;
            float v = 0.0f;
            if (grow < n) v = A[(size_t)grow * K + kc + k];
            if (RELU_IN) v = fmaxf(v + bias_in[kc + k], 0.0f);
            As[k][r] = v;
        }
#pragma unroll
        for (int i = 0; i < (BK * F) / 256; i++) {
            int idx = tid + i * 256;
            int k = idx >> 6;
            int f = idx & 63;
            Ws[k][f] = W[(size_t)(kc + k) * F + f];
        }
        __syncthreads();

#pragma unroll
        for (int k = 0; k < BK; k++) {
            float4 a0 = *(const float4*)&As[k][ty * 8];
            float4 a1 = *(const float4*)&As[k][ty * 8 + 4];
            float4 b  = *(const float4*)&Ws[k][tx * 4];
            float av[8] = {a0.x, a0.y, a0.z, a0.w, a1.x, a1.y, a1.z, a1.w};
            float bv[4] = {b.x, b.y, b.z, b.w};
#pragma unroll
            for (int i = 0; i < 8; i++)
#pragma unroll
                for (int j = 0; j < 4; j++)
                    acc[i][j] = fmaf(av[i], bv[j], acc[i][j]);
        }
        __syncthreads();
    }

#pragma unroll
    for (int i = 0; i < 8; i++) {
        int row = row0 + ty * 8 + i;
        if (row < n) {
            float s = g_dinv[row];
            float4 c = make_float4(acc[i][0] * s, acc[i][1] * s,
                                   acc[i][2] * s, acc[i][3] * s);
            *(float4*)&C[(size_t)row * F + tx * 4] = c;
        }
    }
}

// ---------------------------------------------------------------------------
// CSR gather: one warp per node, h is pre-scaled (hs = h*dinv).
//   o[d] = dinv[d] * ( sum_{s in adj(d)} hs[s] + hs[d] )
// Lanes: f = lane&15 (float4 slot), p = lane>>4 (edge parity); unroll x2 per
// lane -> 4 h-row loads in flight per warp. Tail edges masked (v*0).
// POOL=true: o := relu(o + b2), red.v4-add into summ[dict[d]], cnt[dict[d]]++.
// ---------------------------------------------------------------------------
__device__ __forceinline__ void red_add_v4(float* p, float4 w) {
    asm volatile("red.global.add.v4.f32 [%0], {%1, %2, %3, %4};"
                 :: "l"(p), "f"(w.x), "f"(w.y), "f"(w.z), "f"(w.w)
                 : "memory");
}

template <bool POOL>
__global__ __launch_bounds__(256) void gather_kernel(
    const float* __restrict__ h, float* __restrict__ out_or_summ,
    const float* __restrict__ b2, const int* __restrict__ dict, int n)
{
    int w = (blockIdx.x * blockDim.x + threadIdx.x) >> 5;
    if (w >= n) return;
    int lane = threadIdx.x & 31;
    int f = lane & 15;
    int p = lane >> 4;

    int end = g_off[w];              // post-fill: end of range
    int beg = end - g_deg[w];
    float dv = g_dinv[w];

    float4 acc = make_float4(0.f, 0.f, 0.f, 0.f);

    for (int j = beg + p; j < end; j += 4) {
        int j1 = j + 2;
        int s0 = __ldg(&g_adj[j]);
        bool ok1 = (j1 < end);
        int s1 = ok1 ? __ldg(&g_adj[j1]) : 0;
        float m1 = ok1 ? 1.0f : 0.0f;
        float4 v0 = *(const float4*)(h + (size_t)s0 * F_HID + f * 4);
        float4 v1 = *(const float4*)(h + (size_t)s1 * F_HID + f * 4);
        acc.x += v0.x;
        acc.y += v0.y;
        acc.z += v0.z;
        acc.w += v0.w;
        acc.x = fmaf(v1.x, m1, acc.x);
        acc.y = fmaf(v1.y, m1, acc.y);
        acc.z = fmaf(v1.z, m1, acc.z);
        acc.w = fmaf(v1.w, m1, acc.w);
    }
    // combine the two edge-parity halves (lane f <-> lane f+16)
    acc.x += __shfl_xor_sync(0xffffffffu, acc.x, 16);
    acc.y += __shfl_xor_sync(0xffffffffu, acc.y, 16);
    acc.z += __shfl_xor_sync(0xffffffffu, acc.z, 16);
    acc.w += __shfl_xor_sync(0xffffffffu, acc.w, 16);

    if (p == 0) {
        float4 self = *(const float4*)(h + (size_t)w * F_HID + f * 4);
        float4 o = make_float4(dv * (acc.x + self.x), dv * (acc.y + self.y),
                               dv * (acc.z + self.z), dv * (acc.w + self.w));
        if (POOL) {
            float4 bb = *(const float4*)(b2 + f * 4);
            o.x = fmaxf(o.x + bb.x, 0.0f);
            o.y = fmaxf(o.y + bb.y, 0.0f);
            o.z = fmaxf(o.z + bb.z, 0.0f);
            o.w = fmaxf(o.w + bb.w, 0.0f);
            int d = __ldg(&dict[w]);
            red_add_v4(out_or_summ + (size_t)d * F_HID + f * 4, o);
            if (f == 0) atomicAdd(&g_cnt[d], 1.0f);
        } else {
            *(float4*)(out_or_summ + (size_t)w * F_HID + f * 4) = o;
        }
    }
}

// out = log_softmax( (summ[i] / max(cnt,1)) @ Wfc + bfc )
__global__ __launch_bounds__(256) void final_kernel(
    const float* __restrict__ summ,
    const float* __restrict__ Wfc, const float* __restrict__ bfc,
    float* __restrict__ out, int n)
{
    __shared__ float Wsh[64 * 16];
    __shared__ float bsh[16];
    for (int i = threadIdx.x; i < 64 * 16; i += blockDim.x) Wsh[i] = Wfc[i];
    if (threadIdx.x < 16) bsh[threadIdx.x] = bfc[threadIdx.x];
    __syncthreads();

    int i = blockIdx.x * blockDim.x + threadIdx.x;
    if (i >= n) return;
    float inv = 1.0f / fmaxf(g_cnt[i], 1.0f);

    float lg[16];
#pragma unroll
    for (int j = 0; j < 16; j++) lg[j] = bsh[j];
#pragma unroll
    for (int f = 0; f < 64; f++) {
        float p = summ[(size_t)i * F_HID + f] * inv;
#pragma unroll
        for (int j = 0; j < 16; j++) lg[j] = fmaf(p, Wsh[f * 16 + j], lg[j]);
    }
    float m = lg[0];
#pragma unroll
    for (int j = 1; j < 16; j++) m = fmaxf(m, lg[j]);
    float ssum = 0.0f;
#pragma unroll
    for (int j = 0; j < 16; j++) ssum += expf(lg[j] - m);
    float lse = m + logf(ssum);
#pragma unroll
    for (int j = 0; j < 16; j++) out[(size_t)i * 16 + j] = lg[j] - lse;
}

extern "C" void kernel_launch(void* const* d_in, const int* in_sizes, int n_in,
                              void* d_out, int out_size)
{
    const float* x    = (const float*)d_in[0];
    const int*   edge = (const int*)d_in[1];
    const int*   dict = (const int*)d_in[2];
    const float* W1   = (const float*)d_in[3];
    const float* b1   = (const float*)d_in[4];
    const float* W2   = (const float*)d_in[5];
    const float* b2   = (const float*)d_in[6];
    const float* Wfc  = (const float*)d_in[7];
    const float* bfc  = (const float*)d_in[8];
    float* out = (float*)d_out;

    int n = in_sizes[0] / 128;
    int E = in_sizes[1] / 2;
    if (n > N_MAX) n = N_MAX;
    if (E > E_MAX) E = E_MAX;
    const int* src = edge;
    const int* dst = edge + E;

    void *pA = nullptr, *pB = nullptr, *pDeg = nullptr, *pCnt = nullptr;
    cudaGetSymbolAddress(&pA, g_bufA);
    cudaGetSymbolAddress(&pB, g_bufB);
    cudaGetSymbolAddress(&pDeg, g_deg);
    cudaGetSymbolAddress(&pCnt, g_cnt);
    float* bufA = (float*)pA;
    float* bufB = (float*)pB;

    const int T = 256;
    int gb_n    = (n + T - 1) / T;
    int gb_e4   = ((E + 3) / 4 + T - 1) / T;
    int gb_row  = (n + 127) / 128;
    int gb_gath = (n * 32 + T - 1) / T;
    int nb      = (n + SCAN_B - 1) / SCAN_B;

    // CSR build + normalization terms
    cudaMemsetAsync(pDeg, 0, (size_t)n * sizeof(int));
    count_kernel<<<gb_e4, T>>>(dst, E);
    scan1_kernel<<<nb, SCAN_B>>>(n);          // also computes dinv
    scan2_kernel<<<1, 512>>>(nb);
    scan3_kernel<<<gb_n, T>>>(n);
    fill_kernel<<<gb_e4, T>>>(src, dst, E);   // destructively bumps g_off -> end

    // layer 1: bufA = (x@W1)*dinv ; bufB = raw agg1
    gemm_kernel<128, false><<<gb_row, T>>>(x, W1, b1, bufA, n);
    gather_kernel<false><<<gb_gath, T>>>(bufA, bufB, b2, dict, n);

    // layer 2: bufA = (relu(bufB+b1)@W2)*dinv ; then fused gather+pool -> bufB
    gemm_kernel<64, true><<<gb_row, T>>>(bufB, W2, b1, bufA, n);
    cudaMemsetAsync(pB, 0, (size_t)n * F_HID * sizeof(float));
    cudaMemsetAsync(pCnt, 0, (size_t)n * sizeof(float));
    gather_kernel<true><<<gb_gath, T>>>(bufA, bufB, b2, dict, n);

    // head
    final_kernel<<<gb_n, T>>>(bufB, Wfc, bfc, out, n);
}

// round 11
// speedup vs baseline: 1.5155x; 1.0438x over previous
#include <cuda_runtime.h>
#include <cuda_fp16.h>
#include <cstddef>
#include <cstdint>

// GCN_48129403519136: 2-layer GCN + mean-pool + FC + log_softmax
// CSR-gather, fp16 gather operands, f32x2 packed-FMA GEMMs.
//   hs = (A@W)*dinv[row]  stored as __half (row = 64 halves = 128B)
//   agg[d] = dinv[d] * ( sum_{s in adj(d)} hs[s] + hs[d] )   [fp32 accumulate]
//   gather2 fuses the mean-pool accumulation.
// Flow:
//   deg/scan -> CSR (fill destructively bumps g_off; beg = off-deg)
//   gemm1: bufA(h16) = (x@W1)*dinv
//   gather1: bufB(f32)[d] = dinv[d]*(sum + self)
//   gemm2: bufA(h16) = (relu(bufB+b1)@W2)*dinv
//   gather2+pool: summ(bufB)[dict[d]] += relu(dinv[d]*(sum+self) + b2)
//   final: out = log_softmax((bufB/max(cnt,1))@Wfc + bfc)

#define N_MAX 100000
#define E_MAX 1600000
#define F_HID 64
#define SCAN_B 1024

static __device__ __half g_bufA[N_MAX * F_HID];   // fp16 gather operand
static __device__ float  g_bufB[N_MAX * F_HID];   // fp32 agg / summ
static __device__ float  g_dinv[N_MAX];
static __device__ float  g_cnt[N_MAX];
static __device__ int    g_deg[N_MAX];
static __device__ int    g_off[N_MAX];            // post-fill: END of range
static __device__ int    g_adj[E_MAX];
static __device__ int    g_part[512];

// ---------------------------------------------------------------------------
// packed f32x2 helpers (sm_100a+; ptxas never auto-fuses — PTX only)
// ---------------------------------------------------------------------------
__device__ __forceinline__ void fma2(unsigned long long& d,
                                     unsigned long long a,
                                     unsigned long long b) {
    asm("fma.rn.f32x2 %0, %1, %2, %0;" : "+l"(d) : "l"(a), "l"(b));
}
__device__ __forceinline__ unsigned long long pack2(float lo, float hi) {
    unsigned long long r;
    asm("mov.b64 %0, {%1, %2};" : "=l"(r) : "f"(lo), "f"(hi));
    return r;
}

// ---------------------------------------------------------------------------
// degree count (int4-vectorized)
// ---------------------------------------------------------------------------
__global__ void count_kernel(const int* __restrict__ dst, int E) {
    int t = blockIdx.x * blockDim.x + threadIdx.x;
    int e0 = t * 4;
    if (e0 + 3 < E) {
        int4 d = *(const int4*)(dst + e0);
        atomicAdd(&g_deg[d.x], 1);
        atomicAdd(&g_deg[d.y], 1);
        atomicAdd(&g_deg[d.z], 1);
        atomicAdd(&g_deg[d.w], 1);
    } else {
        for (int e = e0; e < E; e++) atomicAdd(&g_deg[dst[e]], 1);
    }
}

// scan stage 1: per-block exclusive scan of deg -> off; dinv fused
__global__ __launch_bounds__(SCAN_B) void scan1_kernel(int n) {
    __shared__ int sh[SCAN_B];
    int i = blockIdx.x * SCAN_B + threadIdx.x;
    int v = (i < n) ? g_deg[i] : 0;
    if (i < n) g_dinv[i] = rsqrtf((float)v + 1.0f);
    sh[threadIdx.x] = v;
    __syncthreads();
#pragma unroll
    for (int ofs = 1; ofs < SCAN_B; ofs <<= 1) {
        int t = (threadIdx.x >= ofs) ? sh[threadIdx.x - ofs] : 0;
        __syncthreads();
        sh[threadIdx.x] += t;
        __syncthreads();
    }
    if (i < n) g_off[i] = sh[threadIdx.x] - v;
    if (threadIdx.x == SCAN_B - 1) g_part[blockIdx.x] = sh[SCAN_B - 1];
}

// scan stage 2: exclusive scan of block partials (single block)
__global__ __launch_bounds__(512) void scan2_kernel(int nb) {
    __shared__ int sh[512];
    int tid = threadIdx.x;
    int v = (tid < nb) ? g_part[tid] : 0;
    sh[tid] = v;
    __syncthreads();
#pragma unroll
    for (int ofs = 1; ofs < 512; ofs <<= 1) {
        int t = (tid >= ofs) ? sh[tid - ofs] : 0;
        __syncthreads();
        sh[tid] += t;
        __syncthreads();
    }
    if (tid < nb) g_part[tid] = sh[tid] - v;
}

// scan stage 3: add block offsets
__global__ void scan3_kernel(int n) {
    int i = blockIdx.x * blockDim.x + threadIdx.x;
    if (i < n) g_off[i] += g_part[i >> 10];
}

// CSR fill: destructively bumps g_off; afterwards g_off[d] = end of range.
__global__ void fill_kernel(const int* __restrict__ src, const int* __restrict__ dst, int E) {
    int t = blockIdx.x * blockDim.x + threadIdx.x;
    int e0 = t * 4;
    if (e0 + 3 < E) {
        int4 d = *(const int4*)(dst + e0);
        int4 s = *(const int4*)(src + e0);
        g_adj[atomicAdd(&g_off[d.x], 1)] = s.x;
        g_adj[atomicAdd(&g_off[d.y], 1)] = s.y;
        g_adj[atomicAdd(&g_off[d.z], 1)] = s.z;
        g_adj[atomicAdd(&g_off[d.w], 1)] = s.w;
    } else {
        for (int e = e0; e < E; e++)
            g_adj[atomicAdd(&g_off[dst[e]], 1)] = src[e];
    }
}

// ---------------------------------------------------------------------------
// GEMM: C16[n x 64] = half( (A[n x K] @ W[K x 64]) * dinv[row] )
// optional fused relu(a + bias_in[k]) on A-load.
// 256 threads, 128x64 tile, BK=32. Accumulators packed as f32x2 along row
// pairs: acc2[i][j] = (row 2i, row 2i+1) at col tx*4+j. A-pairs come free
// from reinterpreting the float4 smem load; only B needs 4 splat-packs per k.
// ---------------------------------------------------------------------------
template <int K, bool RELU_IN>
__global__ __launch_bounds__(256) void gemm_kernel(
    const float* __restrict__ A, const float* __restrict__ W,
    const float* __restrict__ bias_in, __half* __restrict__ C, int n)
{
    constexpr int F = 64, BK = 32, BM = 128;
    __shared__ float As[BK][BM + 4];
    __shared__ float Ws[BK][F];

    const int tid = threadIdx.x;
    const int tx = tid & 15;
    const int ty = tid >> 4;
    const int row0 = blockIdx.x * BM;

    unsigned long long acc2[4][4];
#pragma unroll
    for (int i = 0; i < 4; i++)
#pragma unroll
        for (int j = 0; j < 4; j++) acc2[i][j] = 0ull;

    for (int kc = 0; kc < K; kc += BK) {
#pragma unroll
        for (int i = 0; i < (BM * BK) / 256; i++) {
            int idx = tid + i * 256;
            int k = idx & (BK - 1);
            int r = idx >> 5;
            int grow = row0 + r;
            float v = 0.0f;
            if (grow < n) v = A[(size_t)grow * K + kc + k];
            if (RELU_IN) v = fmaxf(v + bias_in[kc + k], 0.0f);
            As[k][r] = v;
        }
#pragma unroll
        for (int i = 0; i < (BK * F) / 256; i++) {
            int idx = tid + i * 256;
            int k = idx >> 6;
            int f = idx & 63;
            Ws[k][f] = W[(size_t)(kc + k) * F + f];
        }
        __syncthreads();

#pragma unroll
        for (int k = 0; k < BK; k++) {
            // 8 consecutive A rows -> 4 packed f32x2 operands (free pack)
            union { float4 f; unsigned long long u[2]; } A0, A1;
            A0.f = *(const float4*)&As[k][ty * 8];
            A1.f = *(const float4*)&As[k][ty * 8 + 4];
            unsigned long long av2[4] = {A0.u[0], A0.u[1], A1.u[0], A1.u[1]};
            float4 b = *(const float4*)&Ws[k][tx * 4];
            unsigned long long bv2[4] = {pack2(b.x, b.x), pack2(b.y, b.y),
                                         pack2(b.z, b.z), pack2(b.w, b.w)};
#pragma unroll
            for (int i = 0; i < 4; i++)
#pragma unroll
                for (int j = 0; j < 4; j++)
                    fma2(acc2[i][j], av2[i], bv2[j]);
        }
        __syncthreads();
    }

#pragma unroll
    for (int i = 0; i < 4; i++) {
        union { unsigned long long u; float2 f; } c[4];
#pragma unroll
        for (int j = 0; j < 4; j++) c[j].u = acc2[i][j];
        int r0 = row0 + ty * 8 + 2 * i;
        int r1 = r0 + 1;
        if (r0 < n) {
            float s = g_dinv[r0];
            __half2 h01 = __floats2half2_rn(c[0].f.x * s, c[1].f.x * s);
            __half2 h23 = __floats2half2_rn(c[2].f.x * s, c[3].f.x * s);
            uint2 st = make_uint2(*(unsigned*)&h01, *(unsigned*)&h23);
            *(uint2*)&C[(size_t)r0 * F + tx * 4] = st;
        }
        if (r1 < n) {
            float s = g_dinv[r1];
            __half2 h01 = __floats2half2_rn(c[0].f.y * s, c[1].f.y * s);
            __half2 h23 = __floats2half2_rn(c[2].f.y * s, c[3].f.y * s);
            uint2 st = make_uint2(*(unsigned*)&h01, *(unsigned*)&h23);
            *(uint2*)&C[(size_t)r1 * F + tx * 4] = st;
        }
    }
}

// ---------------------------------------------------------------------------
// CSR gather: one warp per node, h is fp16 pre-scaled (hs = h*dinv, 128B/row).
//   o[d] = dinv[d] * ( sum_{s in adj(d)} hs[s] + hs[d] )   [fp32 accumulate]
// Lanes: f = lane&15 (4 halves each), p = lane>>4 (edge parity); unroll x2
// per lane -> 4 row loads (LDG.64) in flight per warp. Tail masked (v*0).
// POOL=true: o := relu(o + b2), red.v4 into summ[dict[d]], cnt[dict[d]]++.
// ---------------------------------------------------------------------------
__device__ __forceinline__ void red_add_v4(float* p, float4 w) {
    asm volatile("red.global.add.v4.f32 [%0], {%1, %2, %3, %4};"
                 :: "l"(p), "f"(w.x), "f"(w.y), "f"(w.z), "f"(w.w)
                 : "memory");
}

__device__ __forceinline__ float4 ld_h4(const __half* base) {
    uint2 r = *(const uint2*)base;
    __half2 h0 = *(__half2*)&r.x;
    __half2 h1 = *(__half2*)&r.y;
    float2 f0 = __half22float2(h0);
    float2 f1 = __half22float2(h1);
    return make_float4(f0.x, f0.y, f1.x, f1.y);
}

template <bool POOL>
__global__ __launch_bounds__(256) void gather_kernel(
    const __half* __restrict__ h, float* __restrict__ out_or_summ,
    const float* __restrict__ b2, const int* __restrict__ dict, int n)
{
    int w = (blockIdx.x * blockDim.x + threadIdx.x) >> 5;
    if (w >= n) return;
    int lane = threadIdx.x & 31;
    int f = lane & 15;
    int p = lane >> 4;

    int end = g_off[w];
    int beg = end - g_deg[w];
    float dv = g_dinv[w];

    float4 acc = make_float4(0.f, 0.f, 0.f, 0.f);

    for (int j = beg + p; j < end; j += 4) {
        int j1 = j + 2;
        int s0 = __ldg(&g_adj[j]);
        bool ok1 = (j1 < end);
        int s1 = ok1 ? __ldg(&g_adj[j1]) : 0;
        float m1 = ok1 ? 1.0f : 0.0f;
        float4 v0 = ld_h4(h + (size_t)s0 * F_HID + f * 4);
        float4 v1 = ld_h4(h + (size_t)s1 * F_HID + f * 4);
        acc.x += v0.x;
        acc.y += v0.y;
        acc.z += v0.z;
        acc.w += v0.w;
        acc.x = fmaf(v1.x, m1, acc.x);
        acc.y = fmaf(v1.y, m1, acc.y);
        acc.z = fmaf(v1.z, m1, acc.z);
        acc.w = fmaf(v1.w, m1, acc.w);
    }
    acc.x += __shfl_xor_sync(0xffffffffu, acc.x, 16);
    acc.y += __shfl_xor_sync(0xffffffffu, acc.y, 16);
    acc.z += __shfl_xor_sync(0xffffffffu, acc.z, 16);
    acc.w += __shfl_xor_sync(0xffffffffu, acc.w, 16);

    if (p == 0) {
        float4 self = ld_h4(h + (size_t)w * F_HID + f * 4);
        float4 o = make_float4(dv * (acc.x + self.x), dv * (acc.y + self.y),
                               dv * (acc.z + self.z), dv * (acc.w + self.w));
        if (POOL) {
            float4 bb = *(const float4*)(b2 + f * 4);
            o.x = fmaxf(o.x + bb.x, 0.0f);
            o.y = fmaxf(o.y + bb.y, 0.0f);
            o.z = fmaxf(o.z + bb.z, 0.0f);
            o.w = fmaxf(o.w + bb.w, 0.0f);
            int d = __ldg(&dict[w]);
            red_add_v4(out_or_summ + (size_t)d * F_HID + f * 4, o);
            if (f == 0) atomicAdd(&g_cnt[d], 1.0f);
        } else {
            *(float4*)(out_or_summ + (size_t)w * F_HID + f * 4) = o;
        }
    }
}

// out = log_softmax( (summ[i] / max(cnt,1)) @ Wfc + bfc )
__global__ __launch_bounds__(256) void final_kernel(
    const float* __restrict__ summ,
    const float* __restrict__ Wfc, const float* __restrict__ bfc,
    float* __restrict__ out, int n)
{
    __shared__ float Wsh[64 * 16];
    __shared__ float bsh[16];
    for (int i = threadIdx.x; i < 64 * 16; i += blockDim.x) Wsh[i] = Wfc[i];
    if (threadIdx.x < 16) bsh[threadIdx.x] = bfc[threadIdx.x];
    __syncthreads();

    int i = blockIdx.x * blockDim.x + threadIdx.x;
    if (i >= n) return;
    float inv = 1.0f / fmaxf(g_cnt[i], 1.0f);

    float lg[16];
#pragma unroll
    for (int j = 0; j < 16; j++) lg[j] = bsh[j];
#pragma unroll
    for (int f = 0; f < 64; f++) {
        float p = summ[(size_t)i * F_HID + f] * inv;
#pragma unroll
        for (int j = 0; j < 16; j++) lg[j] = fmaf(p, Wsh[f * 16 + j], lg[j]);
    }
    float m = lg[0];
#pragma unroll
    for (int j = 1; j < 16; j++) m = fmaxf(m, lg[j]);
    float ssum = 0.0f;
#pragma unroll
    for (int j = 0; j < 16; j++) ssum += expf(lg[j] - m);
    float lse = m + logf(ssum);
#pragma unroll
    for (int j = 0; j < 16; j++) out[(size_t)i * 16 + j] = lg[j] - lse;
}

extern "C" void kernel_launch(void* const* d_in, const int* in_sizes, int n_in,
                              void* d_out, int out_size)
{
    const float* x    = (const float*)d_in[0];
    const int*   edge = (const int*)d_in[1];
    const int*   dict = (const int*)d_in[2];
    const float* W1   = (const float*)d_in[3];
    const float* b1   = (const float*)d_in[4];
    const float* W2   = (const float*)d_in[5];
    const float* b2   = (const float*)d_in[6];
    const float* Wfc  = (const float*)d_in[7];
    const float* bfc  = (const float*)d_in[8];
    float* out = (float*)d_out;

    int n = in_sizes[0] / 128;
    int E = in_sizes[1] / 2;
    if (n > N_MAX) n = N_MAX;
    if (E > E_MAX) E = E_MAX;
    const int* src = edge;
    const int* dst = edge + E;

    void *pA = nullptr, *pB = nullptr, *pDeg = nullptr, *pCnt = nullptr;
    cudaGetSymbolAddress(&pA, g_bufA);
    cudaGetSymbolAddress(&pB, g_bufB);
    cudaGetSymbolAddress(&pDeg, g_deg);
    cudaGetSymbolAddress(&pCnt, g_cnt);
    __half* bufA = (__half*)pA;
    float*  bufB = (float*)pB;

    const int T = 256;
    int gb_n    = (n + T - 1) / T;
    int gb_e4   = ((E + 3) / 4 + T - 1) / T;
    int gb_row  = (n + 127) / 128;
    int gb_gath = (n * 32 + T - 1) / T;
    int nb      = (n + SCAN_B - 1) / SCAN_B;

    // CSR build + normalization terms
    cudaMemsetAsync(pDeg, 0, (size_t)n * sizeof(int));
    count_kernel<<<gb_e4, T>>>(dst, E);
    scan1_kernel<<<nb, SCAN_B>>>(n);          // also computes dinv
    scan2_kernel<<<1, 512>>>(nb);
    scan3_kernel<<<gb_n, T>>>(n);
    fill_kernel<<<gb_e4, T>>>(src, dst, E);   // destructively bumps g_off -> end

    // layer 1: bufA(h16) = (x@W1)*dinv ; bufB = raw agg1 (fp32)
    gemm_kernel<128, false><<<gb_row, T>>>(x, W1, b1, bufA, n);
    gather_kernel<false><<<gb_gath, T>>>(bufA, bufB, b2, dict, n);

    // layer 2: bufA(h16) = (relu(bufB+b1)@W2)*dinv ; fused gather+pool -> bufB
    gemm_kernel<64, true><<<gb_row, T>>>(bufB, W2, b1, bufA, n);
    cudaMemsetAsync(pB, 0, (size_t)n * F_HID * sizeof(float));
    cudaMemsetAsync(pCnt, 0, (size_t)n * sizeof(float));
    gather_kernel<true><<<gb_gath, T>>>(bufA, bufB, b2, dict, n);

    // head
    final_kernel<<<gb_n, T>>>(bufB, Wfc, bfc, out, n);
}

// round 12
// speedup vs baseline: 1.5165x; 1.0007x over previous
#include <cuda_runtime.h>
#include <cuda_fp16.h>
#include <cstddef>
#include <cstdint>

// GCN_48129403519136: 2-layer GCN + mean-pool + FC + log_softmax
// CSR-gather, fp16 gather operands (LDG.128 rows), f32x2 packed-FMA GEMMs.
//   hs = (A@W)*dinv[row]  stored as __half (row = 64 halves = 128B)
//   agg[d] = dinv[d] * ( sum_{s in adj(d)} hs[s] + hs[d] )   [fp32 accumulate]
//   gather2 fuses the mean-pool accumulation.

#define N_MAX 100000
#define E_MAX 1600000
#define F_HID 64
#define SCAN_B 1024

static __device__ __half g_bufA[N_MAX * F_HID];   // fp16 gather operand
static __device__ float  g_bufB[N_MAX * F_HID];   // fp32 agg / summ
static __device__ float  g_dinv[N_MAX];
static __device__ float  g_cnt[N_MAX];
static __device__ int    g_deg[N_MAX];
static __device__ int    g_off[N_MAX];            // post-fill: END of range
static __device__ int    g_adj[E_MAX];
static __device__ int    g_part[512];

// ---------------------------------------------------------------------------
// packed f32x2 helpers (sm_100a+; ptxas never auto-fuses — PTX only)
// ---------------------------------------------------------------------------
__device__ __forceinline__ void fma2(unsigned long long& d,
                                     unsigned long long a,
                                     unsigned long long b) {
    asm("fma.rn.f32x2 %0, %1, %2, %0;" : "+l"(d) : "l"(a), "l"(b));
}
__device__ __forceinline__ unsigned long long pack2(float lo, float hi) {
    unsigned long long r;
    asm("mov.b64 %0, {%1, %2};" : "=l"(r) : "f"(lo), "f"(hi));
    return r;
}

// ---------------------------------------------------------------------------
// degree count (int4-vectorized)
// ---------------------------------------------------------------------------
__global__ void count_kernel(const int* __restrict__ dst, int E) {
    int t = blockIdx.x * blockDim.x + threadIdx.x;
    int e0 = t * 4;
    if (e0 + 3 < E) {
        int4 d = *(const int4*)(dst + e0);
        atomicAdd(&g_deg[d.x], 1);
        atomicAdd(&g_deg[d.y], 1);
        atomicAdd(&g_deg[d.z], 1);
        atomicAdd(&g_deg[d.w], 1);
    } else {
        for (int e = e0; e < E; e++) atomicAdd(&g_deg[dst[e]], 1);
    }
}

// scan stage 1: per-block exclusive scan of deg -> off; dinv fused
__global__ __launch_bounds__(SCAN_B) void scan1_kernel(int n) {
    __shared__ int sh[SCAN_B];
    int i = blockIdx.x * SCAN_B + threadIdx.x;
    int v = (i < n) ? g_deg[i] : 0;
    if (i < n) g_dinv[i] = rsqrtf((float)v + 1.0f);
    sh[threadIdx.x] = v;
    __syncthreads();
#pragma unroll
    for (int ofs = 1; ofs < SCAN_B; ofs <<= 1) {
        int t = (threadIdx.x >= ofs) ? sh[threadIdx.x - ofs] : 0;
        __syncthreads();
        sh[threadIdx.x] += t;
        __syncthreads();
    }
    if (i < n) g_off[i] = sh[threadIdx.x] - v;
    if (threadIdx.x == SCAN_B - 1) g_part[blockIdx.x] = sh[SCAN_B - 1];
}

// scan stage 2: exclusive scan of block partials (single block)
__global__ __launch_bounds__(512) void scan2_kernel(int nb) {
    __shared__ int sh[512];
    int tid = threadIdx.x;
    int v = (tid < nb) ? g_part[tid] : 0;
    sh[tid] = v;
    __syncthreads();
#pragma unroll
    for (int ofs = 1; ofs < 512; ofs <<= 1) {
        int t = (tid >= ofs) ? sh[tid - ofs] : 0;
        __syncthreads();
        sh[tid] += t;
        __syncthreads();
    }
    if (tid < nb) g_part[tid] = sh[tid] - v;
}

// scan stage 3: add block offsets (int4-vectorized; 1024 % 4 == 0 so all
// four lanes of a vector share the same partial index)
__global__ void scan3_kernel(int n) {
    int t = blockIdx.x * blockDim.x + threadIdx.x;
    int i4 = t * 4;
    if (i4 + 3 < n) {
        int par = g_part[i4 >> 10];
        int4 v = *(const int4*)&g_off[i4];
        v.x += par; v.y += par; v.z += par; v.w += par;
        *(int4*)&g_off[i4] = v;
    } else {
        for (int i = i4; i < n; i++) g_off[i] += g_part[i >> 10];
    }
}

// CSR fill: destructively bumps g_off; afterwards g_off[d] = end of range.
__global__ void fill_kernel(const int* __restrict__ src, const int* __restrict__ dst, int E) {
    int t = blockIdx.x * blockDim.x + threadIdx.x;
    int e0 = t * 4;
    if (e0 + 3 < E) {
        int4 d = *(const int4*)(dst + e0);
        int4 s = *(const int4*)(src + e0);
        g_adj[atomicAdd(&g_off[d.x], 1)] = s.x;
        g_adj[atomicAdd(&g_off[d.y], 1)] = s.y;
        g_adj[atomicAdd(&g_off[d.z], 1)] = s.z;
        g_adj[atomicAdd(&g_off[d.w], 1)] = s.w;
    } else {
        for (int e = e0; e < E; e++)
            g_adj[atomicAdd(&g_off[dst[e]], 1)] = src[e];
    }
}

// ---------------------------------------------------------------------------
// GEMM: C16[n x 64] = half( (A[n x K] @ W[K x 64]) * dinv[row] )
// optional fused relu(a + bias_in[k]) on A-load. f32x2 packed accumulators.
// ---------------------------------------------------------------------------
template <int K, bool RELU_IN>
__global__ __launch_bounds__(256) void gemm_kernel(
    const float* __restrict__ A, const float* __restrict__ W,
    const float* __restrict__ bias_in, __half* __restrict__ C, int n)
{
    constexpr int F = 64, BK = 32, BM = 128;
    __shared__ float As[BK][BM + 4];
    __shared__ float Ws[BK][F];

    const int tid = threadIdx.x;
    const int tx = tid & 15;
    const int ty = tid >> 4;
    const int row0 = blockIdx.x * BM;

    unsigned long long acc2[4][4];
#pragma unroll
    for (int i = 0; i < 4; i++)
#pragma unroll
        for (int j = 0; j < 4; j++) acc2[i][j] = 0ull;

    for (int kc = 0; kc < K; kc += BK) {
#pragma unroll
        for (int i = 0; i < (BM * BK) / 256; i++) {
            int idx = tid + i * 256;
            int k = idx & (BK - 1);
            int r = idx >> 5;
            int grow = row0 + r;
            float v = 0.0f;
            if (grow < n) v = A[(size_t)grow * K + kc + k];
            if (RELU_IN) v = fmaxf(v + bias_in[kc + k], 0.0f);
            As[k][r] = v;
        }
#pragma unroll
        for (int i = 0; i < (BK * F) / 256; i++) {
            int idx = tid + i * 256;
            int k = idx >> 6;
            int f = idx & 63;
            Ws[k][f] = W[(size_t)(kc + k) * F + f];
        }
        __syncthreads();

#pragma unroll
        for (int k = 0; k < BK; k++) {
            union { float4 f; unsigned long long u[2]; } A0, A1;
            A0.f = *(const float4*)&As[k][ty * 8];
            A1.f = *(const float4*)&As[k][ty * 8 + 4];
            unsigned long long av2[4] = {A0.u[0], A0.u[1], A1.u[0], A1.u[1]};
            float4 b = *(const float4*)&Ws[k][tx * 4];
            unsigned long long bv2[4] = {pack2(b.x, b.x), pack2(b.y, b.y),
                                         pack2(b.z, b.z), pack2(b.w, b.w)};
#pragma unroll
            for (int i = 0; i < 4; i++)
#pragma unroll
                for (int j = 0; j < 4; j++)
                    fma2(acc2[i][j], av2[i], bv2[j]);
        }
        __syncthreads();
    }

#pragma unroll
    for (int i = 0; i < 4; i++) {
        union { unsigned long long u; float2 f; } c[4];
#pragma unroll
        for (int j = 0; j < 4; j++) c[j].u = acc2[i][j];
        int r0 = row0 + ty * 8 + 2 * i;
        int r1 = r0 + 1;
        if (r0 < n) {
            float s = g_dinv[r0];
            __half2 h01 = __floats2half2_rn(c[0].f.x * s, c[1].f.x * s);
            __half2 h23 = __floats2half2_rn(c[2].f.x * s, c[3].f.x * s);
            uint2 st = make_uint2(*(unsigned*)&h01, *(unsigned*)&h23);
            *(uint2*)&C[(size_t)r0 * F + tx * 4] = st;
        }
        if (r1 < n) {
            float s = g_dinv[r1];
            __half2 h01 = __floats2half2_rn(c[0].f.y * s, c[1].f.y * s);
            __half2 h23 = __floats2half2_rn(c[2].f.y * s, c[3].f.y * s);
            uint2 st = make_uint2(*(unsigned*)&h01, *(unsigned*)&h23);
            *(uint2*)&C[(size_t)r1 * F + tx * 4] = st;
        }
    }
}

// ---------------------------------------------------------------------------
// CSR gather: one warp per node, fp16 rows loaded as LDG.128.
// Lanes: f = lane&7 (16B = 8 halves each), p = lane>>3 (edge slot 0..3);
// unroll x2 -> 8 rows in flight per warp. Tail masked (v*0).
// Reduce across p with shfl.xor 8,16. POOL=true: fused relu+b2 mean-pool.
// ---------------------------------------------------------------------------
__device__ __forceinline__ void red_add_v4(float* p, float4 w) {
    asm volatile("red.global.add.v4.f32 [%0], {%1, %2, %3, %4};"
                 :: "l"(p), "f"(w.x), "f"(w.y), "f"(w.z), "f"(w.w)
                 : "memory");
}

__device__ __forceinline__ void h8_acc(uint4 r, float m, float* acc) {
    float2 f0 = __half22float2(*(__half2*)&r.x);
    float2 f1 = __half22float2(*(__half2*)&r.y);
    float2 f2 = __half22float2(*(__half2*)&r.z);
    float2 f3 = __half22float2(*(__half2*)&r.w);
    acc[0] = fmaf(f0.x, m, acc[0]);
    acc[1] = fmaf(f0.y, m, acc[1]);
    acc[2] = fmaf(f1.x, m, acc[2]);
    acc[3] = fmaf(f1.y, m, acc[3]);
    acc[4] = fmaf(f2.x, m, acc[4]);
    acc[5] = fmaf(f2.y, m, acc[5]);
    acc[6] = fmaf(f3.x, m, acc[6]);
    acc[7] = fmaf(f3.y, m, acc[7]);
}

template <bool POOL>
__global__ __launch_bounds__(256) void gather_kernel(
    const __half* __restrict__ h, float* __restrict__ out_or_summ,
    const float* __restrict__ b2, const int* __restrict__ dict, int n)
{
    int w = (blockIdx.x * blockDim.x + threadIdx.x) >> 5;
    if (w >= n) return;
    int lane = threadIdx.x & 31;
    int f = lane & 7;          // 16-byte slot within the 128B row
    int p = lane >> 3;         // edge slot 0..3

    int end = g_off[w];
    int beg = end - g_deg[w];
    float dv = g_dinv[w];

    float acc[8];
#pragma unroll
    for (int k = 0; k < 8; k++) acc[k] = 0.0f;

    for (int j = beg + p; j < end; j += 8) {
        int j1 = j + 4;
        int s0 = __ldg(&g_adj[j]);
        bool ok1 = (j1 < end);
        int s1 = ok1 ? __ldg(&g_adj[j1]) : 0;
        float m1 = ok1 ? 1.0f : 0.0f;
        uint4 r0 = *(const uint4*)(h + (size_t)s0 * F_HID + f * 8);
        uint4 r1 = *(const uint4*)(h + (size_t)s1 * F_HID + f * 8);
        h8_acc(r0, 1.0f, acc);
        h8_acc(r1, m1, acc);
    }
    // reduce across the 4 edge slots (p in bits 3..4 of lane)
#pragma unroll
    for (int k = 0; k < 8; k++) {
        acc[k] += __shfl_xor_sync(0xffffffffu, acc[k], 8);
        acc[k] += __shfl_xor_sync(0xffffffffu, acc[k], 16);
    }

    if (p == 0) {
        uint4 rs = *(const uint4*)(h + (size_t)w * F_HID + f * 8);
        float self[8];
#pragma unroll
        for (int k = 0; k < 8; k++) self[k] = 0.0f;
        h8_acc(rs, 1.0f, self);
        float o[8];
#pragma unroll
        for (int k = 0; k < 8; k++) o[k] = dv * (acc[k] + self[k]);

        if (POOL) {
            float4 bb0 = *(const float4*)(b2 + f * 8);
            float4 bb1 = *(const float4*)(b2 + f * 8 + 4);
            float4 o0 = make_float4(fmaxf(o[0] + bb0.x, 0.0f), fmaxf(o[1] + bb0.y, 0.0f),
                                    fmaxf(o[2] + bb0.z, 0.0f), fmaxf(o[3] + bb0.w, 0.0f));
            float4 o1 = make_float4(fmaxf(o[4] + bb1.x, 0.0f), fmaxf(o[5] + bb1.y, 0.0f),
                                    fmaxf(o[6] + bb1.z, 0.0f), fmaxf(o[7] + bb1.w, 0.0f));
            int d = __ldg(&dict[w]);
            red_add_v4(out_or_summ + (size_t)d * F_HID + f * 8, o0);
            red_add_v4(out_or_summ + (size_t)d * F_HID + f * 8 + 4, o1);
            if (lane == 0) atomicAdd(&g_cnt[d], 1.0f);
        } else {
            float4 o0 = make_float4(o[0], o[1], o[2], o[3]);
            float4 o1 = make_float4(o[4], o[5], o[6], o[7]);
            *(float4*)(out_or_summ + (size_t)w * F_HID + f * 8) = o0;
            *(float4*)(out_or_summ + (size_t)w * F_HID + f * 8 + 4) = o1;
        }
    }
}

// out = log_softmax( (summ[i] / max(cnt,1)) @ Wfc + bfc )
__global__ __launch_bounds__(256) void final_kernel(
    const float* __restrict__ summ,
    const float* __restrict__ Wfc, const float* __restrict__ bfc,
    float* __restrict__ out, int n)
{
    __shared__ float Wsh[64 * 16];
    __shared__ float bsh[16];
    for (int i = threadIdx.x; i < 64 * 16; i += blockDim.x) Wsh[i] = Wfc[i];
    if (threadIdx.x < 16) bsh[threadIdx.x] = bfc[threadIdx.x];
    __syncthreads();

    int i = blockIdx.x * blockDim.x + threadIdx.x;
    if (i >= n) return;
    float inv = 1.0f / fmaxf(g_cnt[i], 1.0f);

    float lg[16];
#pragma unroll
    for (int j = 0; j < 16; j++) lg[j] = bsh[j];
#pragma unroll
    for (int f = 0; f < 64; f++) {
        float p = summ[(size_t)i * F_HID + f] * inv;
#pragma unroll
        for (int j = 0; j < 16; j++) lg[j] = fmaf(p, Wsh[f * 16 + j], lg[j]);
    }
    float m = lg[0];
#pragma unroll
    for (int j = 1; j < 16; j++) m = fmaxf(m, lg[j]);
    float ssum = 0.0f;
#pragma unroll
    for (int j = 0; j < 16; j++) ssum += expf(lg[j] - m);
    float lse = m + logf(ssum);
#pragma unroll
    for (int j = 0; j < 16; j++) out[(size_t)i * 16 + j] = lg[j] - lse;
}

extern "C" void kernel_launch(void* const* d_in, const int* in_sizes, int n_in,
                              void* d_out, int out_size)
{
    const float* x    = (const float*)d_in[0];
    const int*   edge = (const int*)d_in[1];
    const int*   dict = (const int*)d_in[2];
    const float* W1   = (const float*)d_in[3];
    const float* b1   = (const float*)d_in[4];
    const float* W2   = (const float*)d_in[5];
    const float* b2   = (const float*)d_in[6];
    const float* Wfc  = (const float*)d_in[7];
    const float* bfc  = (const float*)d_in[8];
    float* out = (float*)d_out;

    int n = in_sizes[0] / 128;
    int E = in_sizes[1] / 2;
    if (n > N_MAX) n = N_MAX;
    if (E > E_MAX) E = E_MAX;
    const int* src = edge;
    const int* dst = edge + E;

    void *pA = nullptr, *pB = nullptr, *pDeg = nullptr, *pCnt = nullptr;
    cudaGetSymbolAddress(&pA, g_bufA);
    cudaGetSymbolAddress(&pB, g_bufB);
    cudaGetSymbolAddress(&pDeg, g_deg);
    cudaGetSymbolAddress(&pCnt, g_cnt);
    __half* bufA = (__half*)pA;
    float*  bufB = (float*)pB;

    const int T = 256;
    int gb_n    = (n + T - 1) / T;
    int gb_n4   = ((n + 3) / 4 + T - 1) / T;
    int gb_e4   = ((E + 3) / 4 + T - 1) / T;
    int gb_row  = (n + 127) / 128;
    int gb_gath = (n * 32 + T - 1) / T;
    int nb      = (n + SCAN_B - 1) / SCAN_B;

    // CSR build + normalization terms
    cudaMemsetAsync(pDeg, 0, (size_t)n * sizeof(int));
    count_kernel<<<gb_e4, T>>>(dst, E);
    scan1_kernel<<<nb, SCAN_B>>>(n);          // also computes dinv
    scan2_kernel<<<1, 512>>>(nb);
    scan3_kernel<<<gb_n4, T>>>(n);
    fill_kernel<<<gb_e4, T>>>(src, dst, E);   // destructively bumps g_off -> end

    // layer 1: bufA(h16) = (x@W1)*dinv ; bufB = raw agg1 (fp32)
    gemm_kernel<128, false><<<gb_row, T>>>(x, W1, b1, bufA, n);
    gather_kernel<false><<<gb_gath, T>>>(bufA, bufB, b2, dict, n);

    // layer 2: bufA(h16) = (relu(bufB+b1)@W2)*dinv ; fused gather+pool -> bufB
    gemm_kernel<64, true><<<gb_row, T>>>(bufB, W2, b1, bufA, n);
    cudaMemsetAsync(pB, 0, (size_t)n * F_HID * sizeof(float));
    cudaMemsetAsync(pCnt, 0, (size_t)n * sizeof(float));
    gather_kernel<true><<<gb_gath, T>>>(bufA, bufB, b2, dict, n);

    // head
    final_kernel<<<gb_n, T>>>(bufB, Wfc, bfc, out, n);
}